// round 10
// baseline (speedup 1.0000x reference)
#include <cuda_runtime.h>
#include <cuda_fp16.h>

#define B_    8
#define CIN   256
#define COUT  256
#define H_    64
#define W_    64
#define L_    4096
#define K2_   9
#define NCH16 144        // 9 k2 * 16 ci-chunks of 16 (B-bake granularity)
#define NCH   72         // 9 k2 * 8  ci-chunks of 32 (GEMM granularity)

// per-buffer smem: A only, 4K (2 sub x 2K)
#define BUF_BYTES 4096

// Scratch (static __device__ arrays — no runtime allocation)
__device__ int4     d_mi[B_ * K2_ * L_];     // bilinear corner indices [b][k2][l]
__device__ float4   d_mw[B_ * K2_ * L_];     // bilinear corner weights (masked)
__device__ unsigned d_Bf[NCH16 * 2048];      // fp16 B frags [chunk16][tile][lane][reg]
__device__ float    d_xT[(size_t)B_ * L_ * CIN];  // x transposed to [b][pixel][ci]

// ---------------------------------------------------------------------------
__device__ __forceinline__ void mma_fp16(float* d, const unsigned* a,
                                         const unsigned* b) {
    asm volatile(
        "mma.sync.aligned.m16n8k16.row.col.f32.f16.f16.f32 "
        "{%0,%1,%2,%3}, {%4,%5,%6,%7}, {%8,%9}, {%0,%1,%2,%3};"
        : "+f"(d[0]), "+f"(d[1]), "+f"(d[2]), "+f"(d[3])
        : "r"(a[0]), "r"(a[1]), "r"(a[2]), "r"(a[3]), "r"(b[0]), "r"(b[1]));
}
__device__ __forceinline__ unsigned pack16(float v0, float v1) {
    __half2 h = __floats2half2_rn(v0, v1);
    return *(unsigned*)&h;
}

// ---------------------------------------------------------------------------
// Kernel 0: transpose x NCHW -> NHWC ([b][ci][l] -> [b][l][ci])
// ---------------------------------------------------------------------------
__global__ void tr_kernel(const float* __restrict__ x) {
    __shared__ float t[32][33];
    const int tx = threadIdx.x & 31, ty = threadIdx.x >> 5;
    const int l0 = blockIdx.x << 5;
    const int c0 = blockIdx.y << 5;
    const int b  = blockIdx.z;
    const float* xb = x + ((size_t)b * CIN + c0) * L_ + l0;
#pragma unroll
    for (int i = 0; i < 4; ++i)
        t[ty + i * 8][tx] = xb[(size_t)(ty + i * 8) * L_ + tx];
    __syncthreads();
    float* ob = d_xT + ((size_t)b * L_ + l0) * CIN + c0;
#pragma unroll
    for (int i = 0; i < 4; ++i)
        ob[(size_t)(ty + i * 8) * CIN + tx] = t[tx][ty + i * 8];
}

// ---------------------------------------------------------------------------
// Kernel 1: bilinear metadata (validated)
// ---------------------------------------------------------------------------
__global__ void meta_kernel(const float* __restrict__ anc) {
    int g = blockIdx.x * blockDim.x + threadIdx.x;
    if (g >= B_ * K2_ * L_) return;
    int l = g % L_, k2 = (g / L_) % K2_, b = g / (L_ * K2_);

    const float* a = anc + (size_t)(b * L_ + l) * 5;
    float xc = a[0] * 0.125f, yc = a[1] * 0.125f;
    float dw = (a[2] * 0.125f) / 3.0f, dh = (a[3] * 0.125f) / 3.0f;
    float s, c;
    sincosf(a[4], &s, &c);
    float fx = (float)(k2 % 3) - 1.0f, fy = (float)(k2 / 3) - 1.0f;
    float xk = dw * fx, yk = dh * fy;
    float px = (c * xk - s * yk) + xc;
    float py = (s * xk + c * yk) + yc;

    float x0f = floorf(px), y0f = floorf(py);
    int x0 = (int)x0f, y0 = (int)y0f;
    float wx1 = px - x0f, wy1 = py - y0f;
    float wx0 = 1.0f - wx1, wy0 = 1.0f - wy1;
    int x1 = x0 + 1, y1 = y0 + 1;
    float vx0 = (x0 >= 0 && x0 < W_) ? 1.f : 0.f;
    float vx1 = (x1 >= 0 && x1 < W_) ? 1.f : 0.f;
    float vy0 = (y0 >= 0 && y0 < H_) ? 1.f : 0.f;
    float vy1 = (y1 >= 0 && y1 < H_) ? 1.f : 0.f;
    int xc0 = min(max(x0, 0), W_ - 1), xc1 = min(max(x1, 0), W_ - 1);
    int yc0 = min(max(y0, 0), H_ - 1), yc1 = min(max(y1, 0), H_ - 1);
    d_mi[g] = make_int4(yc0 * W_ + xc0, yc0 * W_ + xc1,
                        yc1 * W_ + xc0, yc1 * W_ + xc1);
    d_mw[g] = make_float4(wy0 * wx0 * vy0 * vx0, wy0 * wx1 * vy0 * vx1,
                          wy1 * wx0 * vy1 * vx0, wy1 * wx1 * vy1 * vx1);
}

// ---------------------------------------------------------------------------
// Kernel 2: bake B into mma fragment order, single fp16 matrix (validated).
// ---------------------------------------------------------------------------
__global__ void bf_kernel(const float* __restrict__ w) {
    int i = blockIdx.x * blockDim.x + threadIdx.x;
    if (i >= NCH16 * 2048) return;
    int chunk = i >> 11;
    int r2    = i & 2047;
    int tile  = r2 >> 6;
    int lane  = (r2 >> 1) & 31;
    int reg   = r2 & 1;

    int co = tile * 8 + (lane >> 2);
    int kb = 2 * (lane & 3) + 8 * reg;
    int ci = (chunk & 15) * 16 + kb;
    int k2 = chunk >> 4;

    float v0 = w[((size_t)co * CIN + ci) * K2_ + k2];
    float v1 = w[((size_t)co * CIN + ci + 1) * K2_ + k2];
    d_Bf[i] = pack16(v0, v1);
}

// ---------------------------------------------------------------------------
// Kernel 3: implicit GEMM, mma.sync fp16, 32-ci chunks.
//   B fragments loaded DIRECTLY from global into registers (L2/L1-resident,
//   fragment-ordered, coalesced LDG.64) — no B smem round-trip.
//   Smem holds only the A tiles (2 x 4KB double buffer).
// ---------------------------------------------------------------------------
__global__ __launch_bounds__(256, 2)
void gemm_kernel(float* __restrict__ out) {
    __shared__ uint4 smem4[2 * BUF_BYTES / 16];   // 8 KB
    char* smem = (char*)smem4;

    const int tid  = threadIdx.x;
    const int lane = tid & 31;
    const int wid  = tid >> 5;
    const int b    = blockIdx.x >> 6;
    const int l0   = (blockIdx.x & 63) << 6;   // 64-pixel tiles
    const int q    = tid & 7;                  // ci quartet within 32-chunk
    const int pxh  = tid >> 3;                 // pixel (0..31); also handles +32

    // --- producer A STS base offset (pixel pxh, t=0). Variants:
    //     t=1 -> ^16 ; pixel pxh+32 -> +1024
    const int r  = pxh & 15, mt = pxh >> 4;
    const int rs = (r >> 1) & 3;
    const int pk = 2 * (q & 3);
    const int sa0 = (mt * 32 + ((((r & 7) << 2) | (pk & 3)) ^ rs)) * 16
                  + (2 * (pk >= 4) + (r >= 8)) * 4;
    const int suba = (q >> 2) * 2048;          // sub-chunk region

    // --- consumer A fragment base ---
    const int ca0 = (wid & 1) * 1024 + (lane ^ ((lane >> 3) & 3)) * 16;
    // --- B fragment global base for this warp (words) ---
    const int ncol = wid >> 1;
    const unsigned* Bw = d_Bf + (ncol * 8) * 64 + lane * 2;

    float acc[2][8][4];
#pragma unroll
    for (int i = 0; i < 2; ++i)
#pragma unroll
        for (int t = 0; t < 8; ++t)
#pragma unroll
            for (int w0 = 0; w0 < 4; ++w0) acc[i][t][w0] = 0.0f;

    const float* xTb = d_xT + (size_t)b * L_ * CIN;
    int4 mia, mib; float4 mwa, mwb;
    {
        int mx = (b * K2_) * L_ + l0 + pxh;
        mia = d_mi[mx];      mwa = d_mw[mx];
        mib = d_mi[mx + 32]; mwb = d_mw[mx + 32];
    }

    // ---- prologue: chunk 0 A -> buffer 0 ----
    {
        const float* basep = xTb + 4 * q;
        float4 a0 = __ldg((const float4*)(basep + ((size_t)mia.x << 8)));
        float4 a1 = __ldg((const float4*)(basep + ((size_t)mia.y << 8)));
        float4 a2 = __ldg((const float4*)(basep + ((size_t)mia.z << 8)));
        float4 a3 = __ldg((const float4*)(basep + ((size_t)mia.w << 8)));
        float4 c0 = __ldg((const float4*)(basep + ((size_t)mib.x << 8)));
        float4 c1 = __ldg((const float4*)(basep + ((size_t)mib.y << 8)));
        float4 c2 = __ldg((const float4*)(basep + ((size_t)mib.z << 8)));
        float4 c3 = __ldg((const float4*)(basep + ((size_t)mib.w << 8)));
        char* An = smem + suba;
        *(unsigned*)(An + sa0) = pack16(
            mwa.x * a0.x + mwa.y * a1.x + mwa.z * a2.x + mwa.w * a3.x,
            mwa.x * a0.y + mwa.y * a1.y + mwa.z * a2.y + mwa.w * a3.y);
        *(unsigned*)(An + (sa0 ^ 16)) = pack16(
            mwa.x * a0.z + mwa.y * a1.z + mwa.z * a2.z + mwa.w * a3.z,
            mwa.x * a0.w + mwa.y * a1.w + mwa.z * a2.w + mwa.w * a3.w);
        *(unsigned*)(An + 1024 + sa0) = pack16(
            mwb.x * c0.x + mwb.y * c1.x + mwb.z * c2.x + mwb.w * c3.x,
            mwb.x * c0.y + mwb.y * c1.y + mwb.z * c2.y + mwb.w * c3.y);
        *(unsigned*)(An + 1024 + (sa0 ^ 16)) = pack16(
            mwb.x * c0.z + mwb.y * c1.z + mwb.z * c2.z + mwb.w * c3.z,
            mwb.x * c0.w + mwb.y * c1.w + mwb.z * c2.w + mwb.w * c3.w);
    }
    __syncthreads();

    for (int ch = 0; ch < NCH; ++ch) {
        const int buf = ch & 1;
        const bool more = (ch + 1) < NCH;
        float4 a0, a1, a2, a3, c0, c1, c2, c3;
        if (more) {
            const int nc = ch + 1;
            if ((nc & 7) == 0) {
                int mx = (b * K2_ + (nc >> 3)) * L_ + l0 + pxh;
                mia = d_mi[mx];      mwa = d_mw[mx];
                mib = d_mi[mx + 32]; mwb = d_mw[mx + 32];
            }
            const float* basep = xTb + (nc & 7) * 32 + 4 * q;
            a0 = __ldg((const float4*)(basep + ((size_t)mia.x << 8)));
            a1 = __ldg((const float4*)(basep + ((size_t)mia.y << 8)));
            a2 = __ldg((const float4*)(basep + ((size_t)mia.z << 8)));
            a3 = __ldg((const float4*)(basep + ((size_t)mia.w << 8)));
            c0 = __ldg((const float4*)(basep + ((size_t)mib.x << 8)));
            c1 = __ldg((const float4*)(basep + ((size_t)mib.y << 8)));
            c2 = __ldg((const float4*)(basep + ((size_t)mib.z << 8)));
            c3 = __ldg((const float4*)(basep + ((size_t)mib.w << 8)));
        }

        // ---- math: 2 sub-chunks; B fragments straight from global ----
        {
            char* Ab = smem + buf * BUF_BYTES;
            const unsigned* Bc = d_Bf + ch * 4096;
#pragma unroll
            for (int sub = 0; sub < 2; ++sub) {
                const unsigned* Bs = Bc + sub * 2048;
                uint2 bb[8];
#pragma unroll
                for (int t = 0; t < 8; ++t)
                    bb[t] = __ldg((const uint2*)(Bs + (unsigned)(Bw - d_Bf)
                                                  + t * 64) );
                const char* Ar = Ab + sub * 2048;
                uint4 ah0 = *(const uint4*)(Ar + ca0);
                uint4 ah1 = *(const uint4*)(Ar + ca0 + 512);
#pragma unroll
                for (int t = 0; t < 8; ++t) {
                    mma_fp16(acc[0][t], (const unsigned*)&ah0,
                             (const unsigned*)&bb[t]);
                    mma_fp16(acc[1][t], (const unsigned*)&ah1,
                             (const unsigned*)&bb[t]);
                }
            }
        }

        if (more) {
            char* An = smem + (buf ^ 1) * BUF_BYTES + suba;
            *(unsigned*)(An + sa0) = pack16(
                mwa.x * a0.x + mwa.y * a1.x + mwa.z * a2.x + mwa.w * a3.x,
                mwa.x * a0.y + mwa.y * a1.y + mwa.z * a2.y + mwa.w * a3.y);
            *(unsigned*)(An + (sa0 ^ 16)) = pack16(
                mwa.x * a0.z + mwa.y * a1.z + mwa.z * a2.z + mwa.w * a3.z,
                mwa.x * a0.w + mwa.y * a1.w + mwa.z * a2.w + mwa.w * a3.w);
            *(unsigned*)(An + 1024 + sa0) = pack16(
                mwb.x * c0.x + mwb.y * c1.x + mwb.z * c2.x + mwb.w * c3.x,
                mwb.x * c0.y + mwb.y * c1.y + mwb.z * c2.y + mwb.w * c3.y);
            *(unsigned*)(An + 1024 + (sa0 ^ 16)) = pack16(
                mwb.x * c0.z + mwb.y * c1.z + mwb.z * c2.z + mwb.w * c3.z,
                mwb.x * c0.w + mwb.y * c1.w + mwb.z * c2.w + mwb.w * c3.w);
        }
        __syncthreads();
    }

    // ---- epilogue: relu + direct stores (unchanged, validated) ----
#pragma unroll
    for (int i = 0; i < 2; ++i) {
        int pxg = l0 + ((wid & 1) * 2 + i) * 16 + (lane >> 2);
#pragma unroll
        for (int t = 0; t < 8; ++t) {
            int co = ncol * 64 + t * 8 + 2 * (lane & 3);
            float* o0 = out + ((size_t)(b * COUT + co)) * L_ + pxg;
            float* o1 = o0 + L_;
            o0[0] = fmaxf(acc[i][t][0], 0.0f);
            o1[0] = fmaxf(acc[i][t][1], 0.0f);
            o0[8] = fmaxf(acc[i][t][2], 0.0f);
            o1[8] = fmaxf(acc[i][t][3], 0.0f);
        }
    }
}

// ---------------------------------------------------------------------------
extern "C" void kernel_launch(void* const* d_in, const int* in_sizes, int n_in,
                              void* d_out, int out_size) {
    const float* x   = (const float*)d_in[0];  // [8,256,64,64]
    const float* anc = (const float*)d_in[1];  // [8,4096,5]
    const float* w   = (const float*)d_in[2];  // [256,256,3,3]
    float* out = (float*)d_out;                // [8,256,64,64]

    tr_kernel<<<dim3(128, 8, 8), 256>>>(x);
    meta_kernel<<<(B_ * K2_ * L_ + 255) / 256, 256>>>(anc);
    bf_kernel<<<(NCH16 * 2048 + 255) / 256, 256>>>(w);
    gemm_kernel<<<512, 256>>>(out);
}

// round 12
// speedup vs baseline: 1.2122x; 1.2122x over previous
#include <cuda_runtime.h>
#include <cuda_fp16.h>

#define B_    8
#define CIN   256
#define COUT  256
#define H_    64
#define W_    64
#define L_    4096
#define K2_   9
#define NCH16 144        // 9 k2 * 16 ci-chunks of 16 (B-bake granularity)
#define NCH   72         // 9 k2 * 8  ci-chunks of 32
#define NIT   36         // 2 chunks per iteration

// per buffer: A 8KB (2 chunks x 2 sub x 2KB) | B 32KB (2 chunks x 16KB)
#define BUF_BYTES 40960
#define SMEM_BYTES (2 * BUF_BYTES)

// Scratch (static __device__ arrays — no runtime allocation)
__device__ int4     d_mi[B_ * K2_ * L_];     // bilinear corner indices [b][k2][l]
__device__ float4   d_mw[B_ * K2_ * L_];     // bilinear corner weights (masked)
__device__ unsigned d_Bf[NCH16 * 2048];      // fp16 B frags [chunk16][tile][lane][reg]
__device__ float    d_xT[(size_t)B_ * L_ * CIN];  // x transposed to [b][pixel][ci]

// ---------------------------------------------------------------------------
__device__ __forceinline__ void mma_fp16(float* d, const unsigned* a,
                                         const unsigned* b) {
    asm volatile(
        "mma.sync.aligned.m16n8k16.row.col.f32.f16.f16.f32 "
        "{%0,%1,%2,%3}, {%4,%5,%6,%7}, {%8,%9}, {%0,%1,%2,%3};"
        : "+f"(d[0]), "+f"(d[1]), "+f"(d[2]), "+f"(d[3])
        : "r"(a[0]), "r"(a[1]), "r"(a[2]), "r"(a[3]), "r"(b[0]), "r"(b[1]));
}
__device__ __forceinline__ void cp16(unsigned dst, const void* src) {
    asm volatile("cp.async.cg.shared.global [%0], [%1], 16;"
                 :: "r"(dst), "l"(src));
}
#define CP_COMMIT() asm volatile("cp.async.commit_group;" ::: "memory")
#define CP_WAIT0()  asm volatile("cp.async.wait_group 0;" ::: "memory")

__device__ __forceinline__ unsigned pack16(float v0, float v1) {
    __half2 h = __floats2half2_rn(v0, v1);
    return *(unsigned*)&h;
}

// ---------------------------------------------------------------------------
// Kernel 0: transpose x NCHW -> NHWC ([b][ci][l] -> [b][l][ci])
// ---------------------------------------------------------------------------
__global__ void tr_kernel(const float* __restrict__ x) {
    __shared__ float t[32][33];
    const int tx = threadIdx.x & 31, ty = threadIdx.x >> 5;
    const int l0 = blockIdx.x << 5;
    const int c0 = blockIdx.y << 5;
    const int b  = blockIdx.z;
    const float* xb = x + ((size_t)b * CIN + c0) * L_ + l0;
#pragma unroll
    for (int i = 0; i < 4; ++i)
        t[ty + i * 8][tx] = xb[(size_t)(ty + i * 8) * L_ + tx];
    __syncthreads();
    float* ob = d_xT + ((size_t)b * L_ + l0) * CIN + c0;
#pragma unroll
    for (int i = 0; i < 4; ++i)
        ob[(size_t)(ty + i * 8) * CIN + tx] = t[tx][ty + i * 8];
}

// ---------------------------------------------------------------------------
// Kernel 1: bilinear metadata (validated)
// ---------------------------------------------------------------------------
__global__ void meta_kernel(const float* __restrict__ anc) {
    int g = blockIdx.x * blockDim.x + threadIdx.x;
    if (g >= B_ * K2_ * L_) return;
    int l = g % L_, k2 = (g / L_) % K2_, b = g / (L_ * K2_);

    const float* a = anc + (size_t)(b * L_ + l) * 5;
    float xc = a[0] * 0.125f, yc = a[1] * 0.125f;
    float dw = (a[2] * 0.125f) / 3.0f, dh = (a[3] * 0.125f) / 3.0f;
    float s, c;
    sincosf(a[4], &s, &c);
    float fx = (float)(k2 % 3) - 1.0f, fy = (float)(k2 / 3) - 1.0f;
    float xk = dw * fx, yk = dh * fy;
    float px = (c * xk - s * yk) + xc;
    float py = (s * xk + c * yk) + yc;

    float x0f = floorf(px), y0f = floorf(py);
    int x0 = (int)x0f, y0 = (int)y0f;
    float wx1 = px - x0f, wy1 = py - y0f;
    float wx0 = 1.0f - wx1, wy0 = 1.0f - wy1;
    int x1 = x0 + 1, y1 = y0 + 1;
    float vx0 = (x0 >= 0 && x0 < W_) ? 1.f : 0.f;
    float vx1 = (x1 >= 0 && x1 < W_) ? 1.f : 0.f;
    float vy0 = (y0 >= 0 && y0 < H_) ? 1.f : 0.f;
    float vy1 = (y1 >= 0 && y1 < H_) ? 1.f : 0.f;
    int xc0 = min(max(x0, 0), W_ - 1), xc1 = min(max(x1, 0), W_ - 1);
    int yc0 = min(max(y0, 0), H_ - 1), yc1 = min(max(y1, 0), H_ - 1);
    d_mi[g] = make_int4(yc0 * W_ + xc0, yc0 * W_ + xc1,
                        yc1 * W_ + xc0, yc1 * W_ + xc1);
    d_mw[g] = make_float4(wy0 * wx0 * vy0 * vx0, wy0 * wx1 * vy0 * vx1,
                          wy1 * wx0 * vy1 * vx0, wy1 * wx1 * vy1 * vx1);
}

// ---------------------------------------------------------------------------
// Kernel 2: bake B into mma fragment order, single fp16 matrix (validated).
// ---------------------------------------------------------------------------
__global__ void bf_kernel(const float* __restrict__ w) {
    int i = blockIdx.x * blockDim.x + threadIdx.x;
    if (i >= NCH16 * 2048) return;
    int chunk = i >> 11;
    int r2    = i & 2047;
    int tile  = r2 >> 6;
    int lane  = (r2 >> 1) & 31;
    int reg   = r2 & 1;

    int co = tile * 8 + (lane >> 2);
    int kb = 2 * (lane & 3) + 8 * reg;
    int ci = (chunk & 15) * 16 + kb;
    int k2 = chunk >> 4;

    float v0 = w[((size_t)co * CIN + ci) * K2_ + k2];
    float v1 = w[((size_t)co * CIN + ci + 1) * K2_ + k2];
    d_Bf[i] = pack16(v0, v1);
}

// ---------------------------------------------------------------------------
// Kernel 3: implicit GEMM, mma.sync fp16, 2x32-ci chunks per pipeline stage.
//   CTA: M=64 px x N=256 couts, 256 threads (8 warps: 2M x 4N).
//   36 iterations, 1 barrier each; 64 MMAs between barriers.
// ---------------------------------------------------------------------------
__global__ __launch_bounds__(256, 2)
void gemm_kernel(float* __restrict__ out) {
    extern __shared__ uint4 smem4[];
    char* smem = (char*)smem4;
    const unsigned smem_b = (unsigned)__cvta_generic_to_shared(smem);

    const int tid  = threadIdx.x;
    const int lane = tid & 31;
    const int wid  = tid >> 5;
    const int b    = blockIdx.x >> 6;
    const int l0   = (blockIdx.x & 63) << 6;   // 64-pixel tiles
    const int q    = tid & 7;                  // ci quartet within 32-chunk
    const int pxh  = tid >> 3;                 // pixel (0..31); also handles +32

    // --- producer A STS base offset (validated layout) ---
    const int r  = pxh & 15, mt = pxh >> 4;
    const int rs = (r >> 1) & 3;
    const int pk = 2 * (q & 3);
    const int sa0 = (mt * 32 + ((((r & 7) << 2) | (pk & 3)) ^ rs)) * 16
                  + (2 * (pk >= 4) + (r >= 8)) * 4;
    const int suba = (q >> 2) * 2048;          // sub-chunk region

    // --- consumer fragment bases (validated) ---
    const int ca0 = (wid & 1) * 1024 + (lane ^ ((lane >> 3) & 3)) * 16;
    const int bo0 = (wid >> 1) * 2048 + lane * 8;

    float acc[2][8][4];
#pragma unroll
    for (int i = 0; i < 2; ++i)
#pragma unroll
        for (int t = 0; t < 8; ++t)
#pragma unroll
            for (int w0 = 0; w0 < 4; ++w0) acc[i][t][w0] = 0.0f;

    const float* xTb = d_xT + (size_t)b * L_ * CIN;
    int4 mia, mib; float4 mwa, mwb;
    {
        int mx = (b * K2_) * L_ + l0 + pxh;
        mia = d_mi[mx];      mwa = d_mw[mx];
        mib = d_mi[mx + 32]; mwb = d_mw[mx + 32];
    }

    // gather one 32-ci chunk into 8 float4 regs
#define GATHER(cc, A0, A1, A2, A3, C0, C1, C2, C3) do {                      \
        const float* basep = xTb + ((cc) & 7) * 32 + 4 * q;                   \
        A0 = __ldg((const float4*)(basep + ((size_t)mia.x << 8)));            \
        A1 = __ldg((const float4*)(basep + ((size_t)mia.y << 8)));            \
        A2 = __ldg((const float4*)(basep + ((size_t)mia.z << 8)));            \
        A3 = __ldg((const float4*)(basep + ((size_t)mia.w << 8)));            \
        C0 = __ldg((const float4*)(basep + ((size_t)mib.x << 8)));            \
        C1 = __ldg((const float4*)(basep + ((size_t)mib.y << 8)));            \
        C2 = __ldg((const float4*)(basep + ((size_t)mib.z << 8)));            \
        C3 = __ldg((const float4*)(basep + ((size_t)mib.w << 8)));            \
    } while (0)

    // weight+pack+store one gathered chunk into A region at byte base `ab`
#define STORE_A(ab, A0, A1, A2, A3, C0, C1, C2, C3) do {                     \
        char* An = smem + (ab) + suba;                                        \
        *(unsigned*)(An + sa0) = pack16(                                      \
            mwa.x * A0.x + mwa.y * A1.x + mwa.z * A2.x + mwa.w * A3.x,        \
            mwa.x * A0.y + mwa.y * A1.y + mwa.z * A2.y + mwa.w * A3.y);       \
        *(unsigned*)(An + (sa0 ^ 16)) = pack16(                               \
            mwa.x * A0.z + mwa.y * A1.z + mwa.z * A2.z + mwa.w * A3.z,        \
            mwa.x * A0.w + mwa.y * A1.w + mwa.z * A2.w + mwa.w * A3.w);       \
        *(unsigned*)(An + 1024 + sa0) = pack16(                               \
            mwb.x * C0.x + mwb.y * C1.x + mwb.z * C2.x + mwb.w * C3.x,        \
            mwb.x * C0.y + mwb.y * C1.y + mwb.z * C2.y + mwb.w * C3.y);       \
        *(unsigned*)(An + 1024 + (sa0 ^ 16)) = pack16(                        \
            mwb.x * C0.z + mwb.y * C1.z + mwb.z * C2.z + mwb.w * C3.z,        \
            mwb.x * C0.w + mwb.y * C1.w + mwb.z * C2.w + mwb.w * C3.w);       \
    } while (0)

    // math for one chunk: A at byte base `ab`, B at byte base `bb8`
#define MATH(ab, bb8) do {                                                    \
        char* Ab = smem + (ab);                                               \
        char* Bb = smem + (bb8);                                              \
        _Pragma("unroll")                                                     \
        for (int sub = 0; sub < 2; ++sub) {                                   \
            const char* Ar = Ab + sub * 2048;                                 \
            const char* Br = Bb + sub * 8192;                                 \
            uint4 ah0 = *(const uint4*)(Ar + ca0);                            \
            uint4 ah1 = *(const uint4*)(Ar + ca0 + 512);                      \
            uint2 bfr[8];                                                     \
            _Pragma("unroll")                                                 \
            for (int t = 0; t < 8; ++t)                                       \
                bfr[t] = *(const uint2*)(Br + bo0 + t * 256);                 \
            _Pragma("unroll")                                                 \
            for (int t = 0; t < 8; ++t) {                                     \
                mma_fp16(acc[0][t], (const unsigned*)&ah0,                    \
                         (const unsigned*)&bfr[t]);                           \
                mma_fp16(acc[1][t], (const unsigned*)&ah1,                    \
                         (const unsigned*)&bfr[t]);                           \
            }                                                                 \
        }                                                                     \
    } while (0)

    // ---- prologue: chunks 0,1 -> buffer 0 ----
    {
        float4 a0, a1, a2, a3, c0, c1, c2, c3;
#pragma unroll
        for (int i = 0; i < 8; ++i)
            cp16(smem_b + 8192 + (tid + i * 256) * 16,
                 d_Bf + (tid + i * 256) * 4);
        CP_COMMIT();
        GATHER(0, a0, a1, a2, a3, c0, c1, c2, c3);
        STORE_A(0, a0, a1, a2, a3, c0, c1, c2, c3);
        GATHER(1, a0, a1, a2, a3, c0, c1, c2, c3);
        STORE_A(4096, a0, a1, a2, a3, c0, c1, c2, c3);
        CP_WAIT0();
    }
    __syncthreads();

    for (int it = 0; it < NIT; ++it) {
        const int buf = it & 1;
        const int base  = buf * BUF_BYTES;
        const int nbase = (buf ^ 1) * BUF_BYTES;
        const bool more = (it + 1) < NIT;
        float4 a0, a1, a2, a3, c0, c1, c2, c3;

        if (more) {
            const int nc2 = 2 * it + 2;
            if ((nc2 & 7) == 0) {
                int mx = (b * K2_ + (nc2 >> 3)) * L_ + l0 + pxh;
                mia = d_mi[mx];      mwa = d_mw[mx];
                mib = d_mi[mx + 32]; mwb = d_mw[mx + 32];
            }
            GATHER(nc2, a0, a1, a2, a3, c0, c1, c2, c3);
            const unsigned dstB = smem_b + nbase + 8192;
            const unsigned* srcB = d_Bf + nc2 * 4096;
#pragma unroll
            for (int i = 0; i < 8; ++i)
                cp16(dstB + (tid + i * 256) * 16, srcB + (tid + i * 256) * 4);
            CP_COMMIT();
        }

        MATH(base, base + 8192);                  // chunk 2*it

        if (more) {
            STORE_A(nbase, a0, a1, a2, a3, c0, c1, c2, c3);
            GATHER(2 * it + 3, a0, a1, a2, a3, c0, c1, c2, c3);
        }

        MATH(base + 4096, base + 24576);          // chunk 2*it+1

        if (more)
            STORE_A(nbase + 4096, a0, a1, a2, a3, c0, c1, c2, c3);

        CP_WAIT0();
        __syncthreads();
    }

    // ---- epilogue: relu + direct stores (unchanged, validated) ----
    const int ncol = wid >> 1;
#pragma unroll
    for (int i = 0; i < 2; ++i) {
        int pxg = l0 + ((wid & 1) * 2 + i) * 16 + (lane >> 2);
#pragma unroll
        for (int t = 0; t < 8; ++t) {
            int co = ncol * 64 + t * 8 + 2 * (lane & 3);
            float* o0 = out + ((size_t)(b * COUT + co)) * L_ + pxg;
            float* o1 = o0 + L_;
            o0[0] = fmaxf(acc[i][t][0], 0.0f);
            o1[0] = fmaxf(acc[i][t][1], 0.0f);
            o0[8] = fmaxf(acc[i][t][2], 0.0f);
            o1[8] = fmaxf(acc[i][t][3], 0.0f);
        }
    }
}

// ---------------------------------------------------------------------------
extern "C" void kernel_launch(void* const* d_in, const int* in_sizes, int n_in,
                              void* d_out, int out_size) {
    const float* x   = (const float*)d_in[0];  // [8,256,64,64]
    const float* anc = (const float*)d_in[1];  // [8,4096,5]
    const float* w   = (const float*)d_in[2];  // [256,256,3,3]
    float* out = (float*)d_out;                // [8,256,64,64]

    static int configured = 0;
    if (!configured) {
        cudaFuncSetAttribute(gemm_kernel,
                             cudaFuncAttributeMaxDynamicSharedMemorySize,
                             SMEM_BYTES);
        configured = 1;
    }

    tr_kernel<<<dim3(128, 8, 8), 256>>>(x);
    meta_kernel<<<(B_ * K2_ * L_ + 255) / 256, 256>>>(anc);
    bf_kernel<<<(NCH16 * 2048 + 255) / 256, 256>>>(w);
    gemm_kernel<<<512, 256, SMEM_BYTES>>>(out);
}

// round 13
// speedup vs baseline: 1.3092x; 1.0800x over previous
#include <cuda_runtime.h>
#include <cuda_fp16.h>

#define B_    8
#define CIN   256
#define COUT  256
#define H_    64
#define W_    64
#define L_    4096
#define K2_   9
#define NCH16 144        // 9 k2 * 16 ci-chunks of 16 (B-bake granularity)
#define NCH   36         // 9 k2 * 4  ci-chunks of 64 (GEMM granularity)

#define ABUF  16512      // A region: 4 subs * 4112 (+pad)
#define BUF_BYTES (ABUF + 32768)
#define SMEM_BYTES (2 * BUF_BYTES)

// Scratch (static __device__ arrays — no runtime allocation)
__device__ int4     d_mi[B_ * K2_ * L_];     // bilinear corner indices [b][k2][l]
__device__ float4   d_mw[B_ * K2_ * L_];     // bilinear corner weights (masked)
__device__ unsigned d_Bf[NCH16 * 2048];      // fp16 B frags [chunk16][tile][lane][reg]
__device__ __half   d_xT[(size_t)B_ * L_ * CIN];  // x transposed, fp16 [b][pixel][ci]

// ---------------------------------------------------------------------------
__device__ __forceinline__ void mma_fp16(float* d, const unsigned* a,
                                         const unsigned* b) {
    asm volatile(
        "mma.sync.aligned.m16n8k16.row.col.f32.f16.f16.f32 "
        "{%0,%1,%2,%3}, {%4,%5,%6,%7}, {%8,%9}, {%0,%1,%2,%3};"
        : "+f"(d[0]), "+f"(d[1]), "+f"(d[2]), "+f"(d[3])
        : "r"(a[0]), "r"(a[1]), "r"(a[2]), "r"(a[3]), "r"(b[0]), "r"(b[1]));
}
__device__ __forceinline__ void cp16(unsigned dst, const void* src) {
    asm volatile("cp.async.cg.shared.global [%0], [%1], 16;"
                 :: "r"(dst), "l"(src));
}
#define CP_COMMIT() asm volatile("cp.async.commit_group;" ::: "memory")
#define CP_WAIT0()  asm volatile("cp.async.wait_group 0;" ::: "memory")

__device__ __forceinline__ unsigned pack16(float v0, float v1) {
    __half2 h = __floats2half2_rn(v0, v1);
    return *(unsigned*)&h;
}

// weighted bilinear blend of 4 fp16 corner octets -> 4 packed fp16x2 words
__device__ __forceinline__ void blend4(const uint4& g0, const uint4& g1,
                                       const uint4& g2, const uint4& g3,
                                       float4 w, unsigned* o) {
    const __half2* h0 = (const __half2*)&g0;
    const __half2* h1 = (const __half2*)&g1;
    const __half2* h2 = (const __half2*)&g2;
    const __half2* h3 = (const __half2*)&g3;
#pragma unroll
    for (int j = 0; j < 4; ++j) {
        float2 f0 = __half22float2(h0[j]);
        float2 f1 = __half22float2(h1[j]);
        float2 f2 = __half22float2(h2[j]);
        float2 f3 = __half22float2(h3[j]);
        o[j] = pack16(w.x * f0.x + w.y * f1.x + w.z * f2.x + w.w * f3.x,
                      w.x * f0.y + w.y * f1.y + w.z * f2.y + w.w * f3.y);
    }
}

// ---------------------------------------------------------------------------
// Kernel 0: transpose x NCHW -> NHWC fp16 ([b][ci][l] -> [b][l][ci])
// ---------------------------------------------------------------------------
__global__ void tr_kernel(const float* __restrict__ x) {
    __shared__ float t[32][33];
    const int tx = threadIdx.x & 31, ty = threadIdx.x >> 5;
    const int l0 = blockIdx.x << 5;
    const int c0 = blockIdx.y << 5;
    const int b  = blockIdx.z;
    const float* xb = x + ((size_t)b * CIN + c0) * L_ + l0;
#pragma unroll
    for (int i = 0; i < 4; ++i)
        t[ty + i * 8][tx] = xb[(size_t)(ty + i * 8) * L_ + tx];
    __syncthreads();
    __half* ob = d_xT + ((size_t)b * L_ + l0) * CIN + c0;
#pragma unroll
    for (int i = 0; i < 4; ++i)
        ob[(size_t)(ty + i * 8) * CIN + tx] = __float2half_rn(t[tx][ty + i * 8]);
}

// ---------------------------------------------------------------------------
// Kernel 1: bilinear metadata (validated)
// ---------------------------------------------------------------------------
__global__ void meta_kernel(const float* __restrict__ anc) {
    int g = blockIdx.x * blockDim.x + threadIdx.x;
    if (g >= B_ * K2_ * L_) return;
    int l = g % L_, k2 = (g / L_) % K2_, b = g / (L_ * K2_);

    const float* a = anc + (size_t)(b * L_ + l) * 5;
    float xc = a[0] * 0.125f, yc = a[1] * 0.125f;
    float dw = (a[2] * 0.125f) / 3.0f, dh = (a[3] * 0.125f) / 3.0f;
    float s, c;
    sincosf(a[4], &s, &c);
    float fx = (float)(k2 % 3) - 1.0f, fy = (float)(k2 / 3) - 1.0f;
    float xk = dw * fx, yk = dh * fy;
    float px = (c * xk - s * yk) + xc;
    float py = (s * xk + c * yk) + yc;

    float x0f = floorf(px), y0f = floorf(py);
    int x0 = (int)x0f, y0 = (int)y0f;
    float wx1 = px - x0f, wy1 = py - y0f;
    float wx0 = 1.0f - wx1, wy0 = 1.0f - wy1;
    int x1 = x0 + 1, y1 = y0 + 1;
    float vx0 = (x0 >= 0 && x0 < W_) ? 1.f : 0.f;
    float vx1 = (x1 >= 0 && x1 < W_) ? 1.f : 0.f;
    float vy0 = (y0 >= 0 && y0 < H_) ? 1.f : 0.f;
    float vy1 = (y1 >= 0 && y1 < H_) ? 1.f : 0.f;
    int xc0 = min(max(x0, 0), W_ - 1), xc1 = min(max(x1, 0), W_ - 1);
    int yc0 = min(max(y0, 0), H_ - 1), yc1 = min(max(y1, 0), H_ - 1);
    d_mi[g] = make_int4(yc0 * W_ + xc0, yc0 * W_ + xc1,
                        yc1 * W_ + xc0, yc1 * W_ + xc1);
    d_mw[g] = make_float4(wy0 * wx0 * vy0 * vx0, wy0 * wx1 * vy0 * vx1,
                          wy1 * wx0 * vy1 * vx0, wy1 * wx1 * vy1 * vx1);
}

// ---------------------------------------------------------------------------
// Kernel 2: bake B into mma fragment order, single fp16 matrix (validated).
// ---------------------------------------------------------------------------
__global__ void bf_kernel(const float* __restrict__ w) {
    int i = blockIdx.x * blockDim.x + threadIdx.x;
    if (i >= NCH16 * 2048) return;
    int chunk = i >> 11;
    int r2    = i & 2047;
    int tile  = r2 >> 6;
    int lane  = (r2 >> 1) & 31;
    int reg   = r2 & 1;

    int co = tile * 8 + (lane >> 2);
    int kb = 2 * (lane & 3) + 8 * reg;
    int ci = (chunk & 15) * 16 + kb;
    int k2 = chunk >> 4;

    float v0 = w[((size_t)co * CIN + ci) * K2_ + k2];
    float v1 = w[((size_t)co * CIN + ci + 1) * K2_ + k2];
    d_Bf[i] = pack16(v0, v1);
}

// ---------------------------------------------------------------------------
// Kernel 3: implicit GEMM, mma.sync fp16, 64-ci chunks, fp16 gather.
//   CTA: M=128 px x N=256 couts, 512 threads (16 warps: 4M x 4N, warp 32x64).
//   Thread (q=tid&7 -> 8-ci octet, pxh=tid>>3) gathers pixels pxh, pxh+64;
//   each corner LDG.128 covers a full 128B line (4 px per warp-instr).
// ---------------------------------------------------------------------------
__global__ __launch_bounds__(512, 1)
void gemm_kernel(float* __restrict__ out) {
    extern __shared__ uint4 smem4[];
    char* smem = (char*)smem4;
    const unsigned smem_b = (unsigned)__cvta_generic_to_shared(smem);

    const int tid  = threadIdx.x;
    const int lane = tid & 31;
    const int wid  = tid >> 5;
    const int b    = blockIdx.x >> 5;
    const int l0   = (blockIdx.x & 31) << 7;   // 128-pixel tiles
    const int q    = tid & 7;                  // ci octet within 64-chunk
    const int pxh  = tid >> 3;                 // pixel (0..63); also handles +64

    // --- producer A STS offsets (validated granule layout, per-sub bank skew)
    const int r  = pxh & 15, mt = pxh >> 4;    // mt 0..3 (pixel+64 -> +2048B)
    const int rs = (r >> 1) & 3;
    const int sub = q >> 1;                    // 16-ci sub-chunk 0..3
    const int wordoff = (2 * (q & 1) + (r >= 8)) * 4;
    int sa[4];
#pragma unroll
    for (int j = 0; j < 4; ++j)
        sa[j] = sub * 4112
              + (mt * 32 + ((((r & 7) << 2) | j) ^ rs)) * 16 + wordoff;

    // --- consumer fragment bases ---
    const int mtc0 = (wid & 3) * 2;
    const int ca0  = (mtc0 * 32 + (lane ^ ((lane >> 3) & 3))) * 16;
    const int bo0  = (wid >> 2) * 2048 + lane * 8;

    float acc[2][8][4];
#pragma unroll
    for (int i = 0; i < 2; ++i)
#pragma unroll
        for (int t = 0; t < 8; ++t)
#pragma unroll
            for (int w0 = 0; w0 < 4; ++w0) acc[i][t][w0] = 0.0f;

    const __half* xTb = d_xT + (size_t)b * L_ * CIN;
    int4 mia, mib; float4 mwa, mwb;
    {
        int mx = (b * K2_) * L_ + l0 + pxh;
        mia = d_mi[mx];      mwa = d_mw[mx];
        mib = d_mi[mx + 64]; mwb = d_mw[mx + 64];
    }

    // ---- prologue: chunk 0 -> buffer 0 ----
    {
#pragma unroll
        for (int i = 0; i < 4; ++i)
            cp16(smem_b + ABUF + (tid + i * 512) * 16,
                 d_Bf + (tid + i * 512) * 4);
        CP_COMMIT();

        const __half* basep = xTb + 8 * q;
        uint4 a0 = __ldg((const uint4*)(basep + (size_t)mia.x * 256));
        uint4 a1 = __ldg((const uint4*)(basep + (size_t)mia.y * 256));
        uint4 a2 = __ldg((const uint4*)(basep + (size_t)mia.z * 256));
        uint4 a3 = __ldg((const uint4*)(basep + (size_t)mia.w * 256));
        uint4 c0 = __ldg((const uint4*)(basep + (size_t)mib.x * 256));
        uint4 c1 = __ldg((const uint4*)(basep + (size_t)mib.y * 256));
        uint4 c2 = __ldg((const uint4*)(basep + (size_t)mib.z * 256));
        uint4 c3 = __ldg((const uint4*)(basep + (size_t)mib.w * 256));
        unsigned oA[4], oC[4];
        blend4(a0, a1, a2, a3, mwa, oA);
        blend4(c0, c1, c2, c3, mwb, oC);
#pragma unroll
        for (int j = 0; j < 4; ++j) {
            *(unsigned*)(smem + sa[j])        = oA[j];
            *(unsigned*)(smem + sa[j] + 2048) = oC[j];
        }
        CP_WAIT0();
    }
    __syncthreads();

    for (int ch = 0; ch < NCH; ++ch) {
        const int base  = (ch & 1) * BUF_BYTES;
        const int nbase = ((ch & 1) ^ 1) * BUF_BYTES;
        const bool more = (ch + 1) < NCH;
        uint4 a0, a1, a2, a3, c0, c1, c2, c3;

        if (more) {
            const int nc = ch + 1;
            if ((nc & 3) == 0) {
                int mx = (b * K2_ + (nc >> 2)) * L_ + l0 + pxh;
                mia = d_mi[mx];      mwa = d_mw[mx];
                mib = d_mi[mx + 64]; mwb = d_mw[mx + 64];
            }
            const __half* basep = xTb + (nc & 3) * 64 + 8 * q;
            a0 = __ldg((const uint4*)(basep + (size_t)mia.x * 256));
            a1 = __ldg((const uint4*)(basep + (size_t)mia.y * 256));
            a2 = __ldg((const uint4*)(basep + (size_t)mia.z * 256));
            a3 = __ldg((const uint4*)(basep + (size_t)mia.w * 256));
            c0 = __ldg((const uint4*)(basep + (size_t)mib.x * 256));
            c1 = __ldg((const uint4*)(basep + (size_t)mib.y * 256));
            c2 = __ldg((const uint4*)(basep + (size_t)mib.z * 256));
            c3 = __ldg((const uint4*)(basep + (size_t)mib.w * 256));
            const unsigned dstB = smem_b + nbase + ABUF;
            const unsigned* srcB = d_Bf + nc * 8192;
#pragma unroll
            for (int i = 0; i < 4; ++i)
                cp16(dstB + (tid + i * 512) * 16, srcB + (tid + i * 512) * 4);
            CP_COMMIT();
        }

        // ---- math: 4 x 16-ci subs ----
        {
            char* Ab = smem + base;
            char* Bb = smem + base + ABUF;
#pragma unroll
            for (int s = 0; s < 4; ++s) {
                const char* Ar = Ab + s * 4112;
                const char* Br = Bb + s * 8192;
                uint4 ah0 = *(const uint4*)(Ar + ca0);
                uint4 ah1 = *(const uint4*)(Ar + ca0 + 512);
                uint2 bfr[8];
#pragma unroll
                for (int t = 0; t < 8; ++t)
                    bfr[t] = *(const uint2*)(Br + bo0 + t * 256);
#pragma unroll
                for (int t = 0; t < 8; ++t) {
                    mma_fp16(acc[0][t], (const unsigned*)&ah0,
                             (const unsigned*)&bfr[t]);
                    mma_fp16(acc[1][t], (const unsigned*)&ah1,
                             (const unsigned*)&bfr[t]);
                }
            }
        }

        if (more) {
            unsigned oA[4], oC[4];
            blend4(a0, a1, a2, a3, mwa, oA);
            blend4(c0, c1, c2, c3, mwb, oC);
            char* An = smem + nbase;
#pragma unroll
            for (int j = 0; j < 4; ++j) {
                *(unsigned*)(An + sa[j])        = oA[j];
                *(unsigned*)(An + sa[j] + 2048) = oC[j];
            }
        }
        CP_WAIT0();
        __syncthreads();
    }

    // ---- epilogue: relu + direct stores (validated pattern) ----
#pragma unroll
    for (int i = 0; i < 2; ++i) {
        int pxg = l0 + (mtc0 + i) * 16 + (lane >> 2);
#pragma unroll
        for (int t = 0; t < 8; ++t) {
            int co = (wid >> 2) * 64 + t * 8 + 2 * (lane & 3);
            float* o0 = out + ((size_t)(b * COUT + co)) * L_ + pxg;
            float* o1 = o0 + L_;
            o0[0] = fmaxf(acc[i][t][0], 0.0f);
            o1[0] = fmaxf(acc[i][t][1], 0.0f);
            o0[8] = fmaxf(acc[i][t][2], 0.0f);
            o1[8] = fmaxf(acc[i][t][3], 0.0f);
        }
    }
}

// ---------------------------------------------------------------------------
extern "C" void kernel_launch(void* const* d_in, const int* in_sizes, int n_in,
                              void* d_out, int out_size) {
    const float* x   = (const float*)d_in[0];  // [8,256,64,64]
    const float* anc = (const float*)d_in[1];  // [8,4096,5]
    const float* w   = (const float*)d_in[2];  // [256,256,3,3]
    float* out = (float*)d_out;                // [8,256,64,64]

    static int configured = 0;
    if (!configured) {
        cudaFuncSetAttribute(gemm_kernel,
                             cudaFuncAttributeMaxDynamicSharedMemorySize,
                             SMEM_BYTES);
        configured = 1;
    }

    tr_kernel<<<dim3(128, 8, 8), 256>>>(x);
    meta_kernel<<<(B_ * K2_ * L_ + 255) / 256, 256>>>(anc);
    bf_kernel<<<(NCH16 * 2048 + 255) / 256, 256>>>(w);
    gemm_kernel<<<256, 512, SMEM_BYTES>>>(out);
}